// round 9
// baseline (speedup 1.0000x reference)
#include <cuda_runtime.h>
#include <math.h>

#define DIM        256
#define ROWS       64
#define NTHREADS   512
#define H_PITCH    260   // float4-aligned; A-frag reads are warp-broadcast
#define W_PITCH    36    // 36 mod 32 = 4 -> conflict-free float4 reads/stores
#define KB         32
#define NLAYERS    6
#define KCHUNKS    (DIM / KB)   // 8

// smem layout (floats)
#define OFF_H    0
#define OFF_T    (OFF_H + ROWS * H_PITCH)
#define OFF_W0   (OFF_T + ROWS * H_PITCH)
#define OFF_W1   (OFF_W0 + DIM * W_PITCH)
#define OFF_AN   (OFF_W1 + DIM * W_PITCH)
#define OFF_B1   (OFF_AN + 3 * DIM)
#define OFF_B2   (OFF_B1 + DIM)
#define OFF_RED  (OFF_B2 + DIM)          // 64 rows * 8 parts * 4 vals = 2048
#define OFF_CF   (OFF_RED + ROWS * 32)   // 64 rows * 4 coefs
#define SMEM_FLOATS (OFF_CF + ROWS * 4)  // 55296 floats = 221184 B

__device__ __forceinline__ float dot4(float4 a, float4 b) {
    return fmaf(a.x, b.x, fmaf(a.y, b.y, fmaf(a.z, b.z, a.w * b.w)));
}

// ---- W chunk staging: global -> regs -> smem ----
__device__ __forceinline__ void pf_load(float4 pf[4], const float* __restrict__ Wg,
                                        int kc, int t) {
    #pragma unroll
    for (int it = 0; it < 4; it++) {
        int idx = t + it * NTHREADS;   // 0..2047 quads (256 rows x 8 quads)
        int r   = idx >> 3;
        int qq  = idx & 7;
        pf[it] = *(const float4*)(Wg + (size_t)r * DIM + kc * KB + (qq << 2));
    }
}
__device__ __forceinline__ void pf_store(const float4 pf[4], float* sh_W, int t) {
    #pragma unroll
    for (int it = 0; it < 4; it++) {
        int idx = t + it * NTHREADS;
        int r   = idx >> 3;
        int qq  = idx & 7;
        *(float4*)(sh_W + r * W_PITCH + (qq << 2)) = pf[it];
    }
}

// ---- one GEMM: acc[8][4] = Asrc(64xDIM) @ Wg^T, double-buffered via W0/W1 ----
// pf must hold chunk 0 of Wg on entry. One barrier per chunk; STS for chunk
// k+1 overlaps chunk k's FMA stream.
__device__ __forceinline__ void run_gemm(const float* __restrict__ Wg,
                                         const float* __restrict__ Asrc,
                                         float* W0, float* W1, float4 pf[4],
                                         float acc[8][4],
                                         int ty, int nbase, int t) {
    #pragma unroll
    for (int i = 0; i < 8; i++)
        #pragma unroll
        for (int j = 0; j < 4; j++) acc[i][j] = 0.f;

    pf_store(pf, W0, t);   // chunk 0 into buf0 (safe: peers last read buf0 two
                           // barriers ago in the previous GEMM)

    #pragma unroll
    for (int kc = 0; kc < KCHUNKS; kc++) {
        float* cur = (kc & 1) ? W1 : W0;
        if (kc + 1 < KCHUNKS) pf_load(pf, Wg, kc + 1, t);  // LDG hides under sync+compute
        __syncthreads();   // cur's stores visible; prior readers of next buf done

        const float* Ab = Asrc + (ty * 8) * H_PITCH + kc * KB;
        const float* Wb = cur + nbase * W_PITCH;
        #pragma unroll 4
        for (int kq = 0; kq < KB / 4; kq++) {
            float4 b4[4];
            #pragma unroll
            for (int j = 0; j < 4; j++)
                b4[j] = *(const float4*)(Wb + j * 32 * W_PITCH + (kq << 2));
            // two groups of 4 rows -> halves peak live A registers
            #pragma unroll
            for (int g = 0; g < 2; g++) {
                float4 a4[4];
                #pragma unroll
                for (int i = 0; i < 4; i++)
                    a4[i] = *(const float4*)(Ab + (g * 4 + i) * H_PITCH + (kq << 2));
                #pragma unroll
                for (int i = 0; i < 4; i++)
                    #pragma unroll
                    for (int j = 0; j < 4; j++) {
                        float s = acc[g * 4 + i][j];
                        s = fmaf(a4[i].x, b4[j].x, s);
                        s = fmaf(a4[i].y, b4[j].y, s);
                        s = fmaf(a4[i].z, b4[j].z, s);
                        s = fmaf(a4[i].w, b4[j].w, s);
                        acc[g * 4 + i][j] = s;
                    }
            }
        }

        if (kc + 1 < KCHUNKS) pf_store(pf, (kc & 1) ? W0 : W1, t);  // overlaps compute of peers
    }
}

__global__ __launch_bounds__(NTHREADS, 1)
void collapse_engine_kernel(const float* __restrict__ h0,
                            const float* __restrict__ W1g,
                            const float* __restrict__ b1g,
                            const float* __restrict__ W2g,
                            const float* __restrict__ b2g,
                            const float* __restrict__ anchors,
                            float* __restrict__ out_h,
                            float* __restrict__ out_align,
                            float* __restrict__ out_div,
                            float* __restrict__ out_ten,
                            int B)
{
    extern __shared__ float smem[];
    float* sh_h  = smem + OFF_H;
    float* sh_t  = smem + OFF_T;
    float* sh_W0 = smem + OFF_W0;
    float* sh_W1 = smem + OFF_W1;
    float* sh_an = smem + OFF_AN;
    float* sh_b1 = smem + OFF_B1;
    float* sh_b2 = smem + OFF_B2;
    float* sh_rd = smem + OFF_RED;
    float* sh_cf = smem + OFF_CF;

    const int t     = threadIdx.x;
    const int tx    = t & 31;
    const int w     = t >> 5;          // warp 0..15
    const int ty    = w >> 1;          // m-group 0..7 (8 rows each)
    const int nbase = (w & 1) * 128 + tx;
    const int row0  = blockIdx.x * ROWS;

    // ---- stage h tile + anchors + biases ----
    {
        const float4* g = (const float4*)(h0 + (size_t)row0 * DIM);
        #pragma unroll
        for (int it = 0; it < (ROWS * DIM / 4) / NTHREADS; it++) {   // 8
            int q = t + it * NTHREADS;
            int r = q >> 6;            // 64 quads per row
            int c = (q & 63) << 2;
            *(float4*)(sh_h + r * H_PITCH + c) = g[(size_t)r * 64 + (q & 63)];
        }
        for (int i = t; i < 3 * DIM; i += NTHREADS) sh_an[i] = anchors[i];
        for (int i = t; i < DIM; i += NTHREADS) { sh_b1[i] = b1g[i]; sh_b2[i] = b2g[i]; }
    }
    __syncthreads();

    // ---- normalize anchors (3 lanes; once per block, trivial) ----
    if (t < 3) {
        float s = 0.f;
        for (int c = 0; c < DIM; c++) { float v = sh_an[t * DIM + c]; s += v * v; }
        float inv = 1.f / fmaxf(sqrtf(s), 1e-12f);
        for (int c = 0; c < DIM; c++) sh_an[t * DIM + c] *= inv;
    }
    __syncthreads();

    float4 pf[4];
    pf_load(pf, W1g, 0, t);   // W1 chunk0 for layer 0

    for (int layer = 0; layer < NLAYERS; layer++) {
        // ---------- per-row reductions: h.h, h.a0, h.a1, h.a2 ----------
        {
            int r = t & 63;            // row
            int p = t >> 6;            // 32-float segment 0..7
            const float4* hr = (const float4*)(sh_h + r * H_PITCH + p * 32);
            const float4* a0 = (const float4*)(sh_an + p * 32);
            const float4* a1 = (const float4*)(sh_an + DIM + p * 32);
            const float4* a2 = (const float4*)(sh_an + 2 * DIM + p * 32);
            float hh = 0.f, d0 = 0.f, d1 = 0.f, d2 = 0.f;
            #pragma unroll
            for (int q = 0; q < 8; q++) {
                float4 v = hr[q];
                hh += dot4(v, v);
                d0 += dot4(v, a0[q]);
                d1 += dot4(v, a1[q]);
                d2 += dot4(v, a2[q]);
            }
            float* red = sh_rd + (r * 8 + p) * 4;
            red[0] = hh; red[1] = d0; red[2] = d1; red[3] = d2;
        }
        __syncthreads();

        // combine per row; traces + force coefficients
        if (t < ROWS) {
            const float* red = sh_rd + t * 32;
            float hh = 0.f, d0 = 0.f, d1 = 0.f, d2 = 0.f;
            #pragma unroll
            for (int p = 0; p < 8; p++) {
                hh += red[p * 4 + 0]; d0 += red[p * 4 + 1];
                d1 += red[p * 4 + 2]; d2 += red[p * 4 + 3];
            }
            float invn = 1.f / fmaxf(sqrtf(hh), 1e-12f);
            float al0 = d0 * invn, al1 = d1 * invn, al2 = d2 * invn;
            float dv0 = 1.f - al0, dv1 = 1.f - al1, dv2 = 1.f - al2;

            size_t base = ((size_t)layer * B + (row0 + t)) * 3;
            out_align[base + 0] = al0; out_align[base + 1] = al1; out_align[base + 2] = al2;
            out_div[base + 0] = dv0;  out_div[base + 1] = dv1;  out_div[base + 2] = dv2;
            out_ten[base + 0] = fabsf(dv0); out_ten[base + 1] = fabsf(dv1); out_ten[base + 2] = fabsf(dv2);

            // ||h - a||^2 = hh - 2 h.a + 1  (anchors unit)
            float r0 = sqrtf(fmaxf(hh - 2.f * d0 + 1.f, 0.f));
            float r1 = sqrtf(fmaxf(hh - 2.f * d1 + 1.f, 0.f));
            float r2 = sqrtf(fmaxf(hh - 2.f * d2 + 1.f, 0.f));
            float q0 = 0.1f * dv0 / fmaxf(r0, 1e-12f);
            float q1 = 0.1f * dv1 / fmaxf(r1, 1e-12f);
            float q2 = 0.1f * dv2 / fmaxf(r2, 1e-12f);
            float* cf = sh_cf + t * 4;
            cf[0] = 1.f - (q0 + q1 + q2);        // coefficient of h
            cf[1] = q0; cf[2] = q1; cf[3] = q2;  // coefficients of anchors
        }

        float acc[8][4];

        // ---------- GEMM1: sh_t = tanh(sh_h @ W1^T + b1) ----------
        run_gemm(W1g, sh_h, sh_W0, sh_W1, pf, acc, ty, nbase, t);

        pf_load(pf, W2g, 0, t);   // W2 chunk0, hidden under epilogue

        #pragma unroll
        for (int i = 0; i < 8; i++) {
            int m = ty * 8 + i;
            #pragma unroll
            for (int j = 0; j < 4; j++) {
                int n = nbase + 32 * j;
                sh_t[m * H_PITCH + n] = tanhf(acc[i][j] + sh_b1[n]);
            }
        }
        // (run_gemm's chunk-0 barrier orders these sh_t writes before GEMM2 reads)

        // ---------- GEMM2 + fused update ----------
        run_gemm(W2g, sh_t, sh_W0, sh_W1, pf, acc, ty, nbase, t);

        if (layer + 1 < NLAYERS)
            pf_load(pf, W1g, 0, t);   // next layer's W1 chunk0, hidden under epilogue+norm

        // epilogue: h_new = cf0*h + (acc + b2) + sum g_a * anchor_a, in place
        // (safe without a barrier: GEMM2 compute reads only sh_t/sh_W*, and each
        //  sh_h element is read+written only by its owning thread)
        #pragma unroll
        for (int i = 0; i < 8; i++) {
            int m = ty * 8 + i;
            const float* cf = sh_cf + m * 4;
            float c0 = cf[0], g0 = cf[1], g1 = cf[2], g2 = cf[3];
            #pragma unroll
            for (int j = 0; j < 4; j++) {
                int n = nbase + 32 * j;
                float hv = sh_h[m * H_PITCH + n];
                float v = acc[i][j] + sh_b2[n];
                v = fmaf(c0, hv, v);
                v = fmaf(g0, sh_an[n], v);
                v = fmaf(g1, sh_an[DIM + n], v);
                v = fmaf(g2, sh_an[2 * DIM + n], v);
                sh_h[m * H_PITCH + n] = v;
            }
        }
        __syncthreads();

        // ---------- norm clip ----------
        {
            int r = t & 63;
            int p = t >> 6;
            const float4* hr = (const float4*)(sh_h + r * H_PITCH + p * 32);
            float hh = 0.f;
            #pragma unroll
            for (int q = 0; q < 8; q++) { float4 v = hr[q]; hh += dot4(v, v); }
            sh_rd[r * 8 + p] = hh;
        }
        __syncthreads();
        if (t < ROWS) {
            float hh = 0.f;
            #pragma unroll
            for (int p = 0; p < 8; p++) hh += sh_rd[t * 8 + p];
            float n = sqrtf(hh);
            sh_cf[t] = (n > 10.0f) ? (10.0f / (n + 1e-8f)) : 1.0f;  // cf slot reuse safe here
        }
        __syncthreads();
        {   // scale rows (s==1 when not clipped)
            #pragma unroll
            for (int it = 0; it < (ROWS * 64) / NTHREADS; it++) {   // 8
                int q = t + it * NTHREADS;
                int r = q >> 6;
                int c = (q & 63) << 2;
                float s = sh_cf[r];
                float4* p4 = (float4*)(sh_h + r * H_PITCH + c);
                float4 v = *p4;
                v.x *= s; v.y *= s; v.z *= s; v.w *= s;
                *p4 = v;
            }
        }
        __syncthreads();
    }

    // ---- write h_final ----
    {
        float4* g = (float4*)(out_h + (size_t)row0 * DIM);
        #pragma unroll
        for (int it = 0; it < (ROWS * DIM / 4) / NTHREADS; it++) {   // 8
            int q = t + it * NTHREADS;
            int r = q >> 6;
            int qq = q & 63;
            g[(size_t)r * 64 + qq] = *(float4*)(sh_h + r * H_PITCH + (qq << 2));
        }
    }
}

extern "C" void kernel_launch(void* const* d_in, const int* in_sizes, int n_in,
                              void* d_out, int out_size)
{
    const float* h0      = (const float*)d_in[0];
    const float* W1      = (const float*)d_in[1];
    const float* b1      = (const float*)d_in[2];
    const float* W2      = (const float*)d_in[3];
    const float* b2      = (const float*)d_in[4];
    const float* anchors = (const float*)d_in[5];

    const int B = in_sizes[0] / DIM;

    float* out       = (float*)d_out;
    float* out_h     = out;                                  // [B, 256]
    float* out_align = out_h + (size_t)B * DIM;              // [6, B, 3]
    float* out_div   = out_align + (size_t)NLAYERS * B * 3;  // [6, B, 3]
    float* out_ten   = out_div + (size_t)NLAYERS * B * 3;    // [6, B, 3]

    const size_t smem_bytes = (size_t)SMEM_FLOATS * sizeof(float);  // ~216 KB
    cudaFuncSetAttribute(collapse_engine_kernel,
                         cudaFuncAttributeMaxDynamicSharedMemorySize,
                         (int)smem_bytes);

    collapse_engine_kernel<<<B / ROWS, NTHREADS, smem_bytes>>>(
        h0, W1, b1, W2, b2, anchors,
        out_h, out_align, out_div, out_ten, B);
}

// round 12
// speedup vs baseline: 1.0806x; 1.0806x over previous
#include <cuda_runtime.h>
#include <math.h>

#define DIM        256
#define ROWS       64
#define NTHREADS   256
#define H_PITCH    260   // float4-aligned; A-frag reads are warp-broadcast
#define W_PITCH    36    // 36 mod 32 = 4 -> conflict-free float4 reads/stores
#define KB         32
#define NLAYERS    6
#define KCHUNKS    (DIM / KB)   // 8

// smem layout (floats)
#define OFF_H    0
#define OFF_T    (OFF_H + ROWS * H_PITCH)
#define OFF_W0   (OFF_T + ROWS * H_PITCH)
#define OFF_W1   (OFF_W0 + DIM * W_PITCH)
#define OFF_AN   (OFF_W1 + DIM * W_PITCH)
#define OFF_B1   (OFF_AN + 3 * DIM)
#define OFF_B2   (OFF_B1 + DIM)
#define OFF_RED  (OFF_B2 + DIM)          // 64 rows * 4 parts * 4 vals = 1024
#define OFF_CF   (OFF_RED + ROWS * 16)   // 64 rows * 4 coefs
#define SMEM_FLOATS (OFF_CF + ROWS * 4)  // 54272 floats = 217088 B

__device__ __forceinline__ float dot4(float4 a, float4 b) {
    return fmaf(a.x, b.x, fmaf(a.y, b.y, fmaf(a.z, b.z, a.w * b.w)));
}

// ---- W chunk staging: global -> regs -> smem (8 quads/thread at 256 thr) ----
__device__ __forceinline__ void pf_load(float4 pf[8], const float* __restrict__ Wg,
                                        int kc, int t) {
    #pragma unroll
    for (int it = 0; it < 8; it++) {
        int idx = t + it * NTHREADS;   // 0..2047 quads (256 rows x 8 quads)
        int r   = idx >> 3;
        int qq  = idx & 7;
        pf[it] = *(const float4*)(Wg + (size_t)r * DIM + kc * KB + (qq << 2));
    }
}
__device__ __forceinline__ void pf_store(const float4 pf[8], float* sh_W, int t) {
    #pragma unroll
    for (int it = 0; it < 8; it++) {
        int idx = t + it * NTHREADS;
        int r   = idx >> 3;
        int qq  = idx & 7;
        *(float4*)(sh_W + r * W_PITCH + (qq << 2)) = pf[it];
    }
}

// ---- one GEMM: acc[8][8] = Asrc(64xDIM) @ Wg^T, double-buffered via W0/W1 ----
// pf must hold chunk 0 of Wg on entry. One barrier per chunk; STS for chunk
// k+1 and LDG for chunk k+1 both overlap compute.
__device__ __forceinline__ void run_gemm(const float* __restrict__ Wg,
                                         const float* __restrict__ Asrc,
                                         float* W0, float* W1, float4 pf[8],
                                         float acc[8][8],
                                         int ty, int tx, int t) {
    #pragma unroll
    for (int i = 0; i < 8; i++)
        #pragma unroll
        for (int j = 0; j < 8; j++) acc[i][j] = 0.f;

    pf_store(pf, W0, t);   // chunk 0 into buf0 (last readers fenced >=1 barrier ago)

    for (int kc = 0; kc < KCHUNKS; kc++) {
        float* cur = (kc & 1) ? W1 : W0;
        if (kc + 1 < KCHUNKS) pf_load(pf, Wg, kc + 1, t);  // LDG hides under sync+compute
        __syncthreads();   // cur's stores visible; prior readers of other buf done

        const float* Ab = Asrc + (ty * 8) * H_PITCH + kc * KB;
        const float* Wb = cur + tx * W_PITCH;
        #pragma unroll 2
        for (int kq = 0; kq < KB / 4; kq++) {
            float4 a4[8], b4[8];
            #pragma unroll
            for (int i = 0; i < 8; i++)
                a4[i] = *(const float4*)(Ab + i * H_PITCH + (kq << 2));
            #pragma unroll
            for (int j = 0; j < 8; j++)
                b4[j] = *(const float4*)(Wb + j * 32 * W_PITCH + (kq << 2));
            #pragma unroll
            for (int i = 0; i < 8; i++)
                #pragma unroll
                for (int j = 0; j < 8; j++) {
                    float s = acc[i][j];
                    s = fmaf(a4[i].x, b4[j].x, s);
                    s = fmaf(a4[i].y, b4[j].y, s);
                    s = fmaf(a4[i].z, b4[j].z, s);
                    s = fmaf(a4[i].w, b4[j].w, s);
                    acc[i][j] = s;
                }
        }

        if (kc + 1 < KCHUNKS) pf_store(pf, (kc & 1) ? W0 : W1, t);  // overlaps peers' compute
    }
}

__global__ __launch_bounds__(NTHREADS, 1)
void collapse_engine_kernel(const float* __restrict__ h0,
                            const float* __restrict__ W1g,
                            const float* __restrict__ b1g,
                            const float* __restrict__ W2g,
                            const float* __restrict__ b2g,
                            const float* __restrict__ anchors,
                            float* __restrict__ out_h,
                            float* __restrict__ out_align,
                            float* __restrict__ out_div,
                            float* __restrict__ out_ten,
                            int B)
{
    extern __shared__ float smem[];
    float* sh_h  = smem + OFF_H;
    float* sh_t  = smem + OFF_T;
    float* sh_W0 = smem + OFF_W0;
    float* sh_W1 = smem + OFF_W1;
    float* sh_an = smem + OFF_AN;
    float* sh_b1 = smem + OFF_B1;
    float* sh_b2 = smem + OFF_B2;
    float* sh_rd = smem + OFF_RED;
    float* sh_cf = smem + OFF_CF;

    const int t   = threadIdx.x;
    const int tx  = t & 31;   // n-dim lane
    const int ty  = t >> 5;   // m-group (warp id), 8 rows each
    const int row0 = blockIdx.x * ROWS;

    // ---- stage h tile + anchors + biases ----
    {
        const float4* g = (const float4*)(h0 + (size_t)row0 * DIM);
        #pragma unroll
        for (int it = 0; it < (ROWS * DIM / 4) / NTHREADS; it++) {   // 16
            int q = t + it * NTHREADS;
            int r = q >> 6;            // 64 quads per row
            int c = (q & 63) << 2;
            *(float4*)(sh_h + r * H_PITCH + c) = g[(size_t)r * 64 + (q & 63)];
        }
        for (int i = t; i < 3 * DIM; i += NTHREADS) sh_an[i] = anchors[i];
        for (int i = t; i < DIM; i += NTHREADS) { sh_b1[i] = b1g[i]; sh_b2[i] = b2g[i]; }
    }
    __syncthreads();

    // ---- normalize anchors (3 lanes; once per block, trivial) ----
    if (t < 3) {
        float s = 0.f;
        for (int c = 0; c < DIM; c++) { float v = sh_an[t * DIM + c]; s += v * v; }
        float inv = 1.f / fmaxf(sqrtf(s), 1e-12f);
        for (int c = 0; c < DIM; c++) sh_an[t * DIM + c] *= inv;
    }
    __syncthreads();

    float4 pf[8];
    pf_load(pf, W1g, 0, t);   // W1 chunk0 for layer 0

    for (int layer = 0; layer < NLAYERS; layer++) {
        // ---------- per-row reductions: h.h, h.a0, h.a1, h.a2 ----------
        {
            int r = t & 63;            // row
            int p = t >> 6;            // 64-float segment 0..3
            const float4* hr = (const float4*)(sh_h + r * H_PITCH + p * 64);
            const float4* a0 = (const float4*)(sh_an + p * 64);
            const float4* a1 = (const float4*)(sh_an + DIM + p * 64);
            const float4* a2 = (const float4*)(sh_an + 2 * DIM + p * 64);
            float hh = 0.f, d0 = 0.f, d1 = 0.f, d2 = 0.f;
            #pragma unroll
            for (int q = 0; q < 16; q++) {
                float4 v = hr[q];
                hh += dot4(v, v);
                d0 += dot4(v, a0[q]);
                d1 += dot4(v, a1[q]);
                d2 += dot4(v, a2[q]);
            }
            float* red = sh_rd + (r * 4 + p) * 4;
            red[0] = hh; red[1] = d0; red[2] = d1; red[3] = d2;
        }
        __syncthreads();

        // combine per row; traces + force coefficients
        if (t < ROWS) {
            const float* red = sh_rd + t * 16;
            float hh = red[0] + red[4] + red[8]  + red[12];
            float d0 = red[1] + red[5] + red[9]  + red[13];
            float d1 = red[2] + red[6] + red[10] + red[14];
            float d2 = red[3] + red[7] + red[11] + red[15];
            float invn = 1.f / fmaxf(sqrtf(hh), 1e-12f);
            float al0 = d0 * invn, al1 = d1 * invn, al2 = d2 * invn;
            float dv0 = 1.f - al0, dv1 = 1.f - al1, dv2 = 1.f - al2;

            size_t base = ((size_t)layer * B + (row0 + t)) * 3;
            out_align[base + 0] = al0; out_align[base + 1] = al1; out_align[base + 2] = al2;
            out_div[base + 0] = dv0;  out_div[base + 1] = dv1;  out_div[base + 2] = dv2;
            out_ten[base + 0] = fabsf(dv0); out_ten[base + 1] = fabsf(dv1); out_ten[base + 2] = fabsf(dv2);

            // ||h - a||^2 = hh - 2 h.a + 1  (anchors unit)
            float r0 = sqrtf(fmaxf(hh - 2.f * d0 + 1.f, 0.f));
            float r1 = sqrtf(fmaxf(hh - 2.f * d1 + 1.f, 0.f));
            float r2 = sqrtf(fmaxf(hh - 2.f * d2 + 1.f, 0.f));
            float q0 = 0.1f * dv0 / fmaxf(r0, 1e-12f);
            float q1 = 0.1f * dv1 / fmaxf(r1, 1e-12f);
            float q2 = 0.1f * dv2 / fmaxf(r2, 1e-12f);
            float* cf = sh_cf + t * 4;
            cf[0] = 1.f - (q0 + q1 + q2);        // coefficient of h
            cf[1] = q0; cf[2] = q1; cf[3] = q2;  // coefficients of anchors
        }

        float acc[8][8];

        // ---------- GEMM1: sh_t = tanh(sh_h @ W1^T + b1) ----------
        run_gemm(W1g, sh_h, sh_W0, sh_W1, pf, acc, ty, tx, t);

        pf_load(pf, W2g, 0, t);   // W2 chunk0, hidden under epilogue

        #pragma unroll
        for (int i = 0; i < 8; i++) {
            int m = ty * 8 + i;
            #pragma unroll
            for (int j = 0; j < 8; j++) {
                int n = tx + 32 * j;
                sh_t[m * H_PITCH + n] = tanhf(acc[i][j] + sh_b1[n]);
            }
        }
        // (run_gemm's chunk-0 barrier orders these sh_t writes before GEMM2 reads)

        // ---------- GEMM2 + fused update ----------
        run_gemm(W2g, sh_t, sh_W0, sh_W1, pf, acc, ty, tx, t);

        if (layer + 1 < NLAYERS)
            pf_load(pf, W1g, 0, t);   // next layer's W1 chunk0, hidden under epilogue+norm

        // epilogue: h_new = cf0*h + (acc + b2) + sum g_a * anchor_a, in place
        // (safe without a barrier: GEMM2 compute reads only sh_t/sh_W*, and each
        //  sh_h element is read+written only by its owning thread)
        #pragma unroll
        for (int i = 0; i < 8; i++) {
            int m = ty * 8 + i;
            const float* cf = sh_cf + m * 4;
            float c0 = cf[0], g0 = cf[1], g1 = cf[2], g2 = cf[3];
            #pragma unroll
            for (int j = 0; j < 8; j++) {
                int n = tx + 32 * j;
                float hv = sh_h[m * H_PITCH + n];
                float v = acc[i][j] + sh_b2[n];
                v = fmaf(c0, hv, v);
                v = fmaf(g0, sh_an[n], v);
                v = fmaf(g1, sh_an[DIM + n], v);
                v = fmaf(g2, sh_an[2 * DIM + n], v);
                sh_h[m * H_PITCH + n] = v;
            }
        }
        __syncthreads();

        // ---------- norm clip ----------
        {
            int r = t & 63;
            int p = t >> 6;
            const float4* hr = (const float4*)(sh_h + r * H_PITCH + p * 64);
            float hh = 0.f;
            #pragma unroll
            for (int q = 0; q < 16; q++) { float4 v = hr[q]; hh += dot4(v, v); }
            sh_rd[r * 4 + p] = hh;
        }
        __syncthreads();
        if (t < ROWS) {
            float hh = sh_rd[t * 4] + sh_rd[t * 4 + 1] + sh_rd[t * 4 + 2] + sh_rd[t * 4 + 3];
            float n = sqrtf(hh);
            sh_cf[t] = (n > 10.0f) ? (10.0f / (n + 1e-8f)) : 1.0f;  // cf slot reuse safe here
        }
        __syncthreads();
        {   // scale rows (s==1 when not clipped)
            #pragma unroll
            for (int it = 0; it < (ROWS * 64) / NTHREADS; it++) {   // 16
                int q = t + it * NTHREADS;
                int r = q >> 6;
                int c = (q & 63) << 2;
                float s = sh_cf[r];
                float4* p4 = (float4*)(sh_h + r * H_PITCH + c);
                float4 v = *p4;
                v.x *= s; v.y *= s; v.z *= s; v.w *= s;
                *p4 = v;
            }
        }
        __syncthreads();
    }

    // ---- write h_final ----
    {
        float4* g = (float4*)(out_h + (size_t)row0 * DIM);
        #pragma unroll
        for (int it = 0; it < (ROWS * DIM / 4) / NTHREADS; it++) {   // 16
            int q = t + it * NTHREADS;
            int r = q >> 6;
            int qq = q & 63;
            g[(size_t)r * 64 + qq] = *(float4*)(sh_h + r * H_PITCH + (qq << 2));
        }
    }
}

extern "C" void kernel_launch(void* const* d_in, const int* in_sizes, int n_in,
                              void* d_out, int out_size)
{
    const float* h0      = (const float*)d_in[0];
    const float* W1      = (const float*)d_in[1];
    const float* b1      = (const float*)d_in[2];
    const float* W2      = (const float*)d_in[3];
    const float* b2      = (const float*)d_in[4];
    const float* anchors = (const float*)d_in[5];

    const int B = in_sizes[0] / DIM;

    float* out       = (float*)d_out;
    float* out_h     = out;                                  // [B, 256]
    float* out_align = out_h + (size_t)B * DIM;              // [6, B, 3]
    float* out_div   = out_align + (size_t)NLAYERS * B * 3;  // [6, B, 3]
    float* out_ten   = out_div + (size_t)NLAYERS * B * 3;    // [6, B, 3]

    const size_t smem_bytes = (size_t)SMEM_FLOATS * sizeof(float);  // ~217 KB
    cudaFuncSetAttribute(collapse_engine_kernel,
                         cudaFuncAttributeMaxDynamicSharedMemorySize,
                         (int)smem_bytes);

    collapse_engine_kernel<<<B / ROWS, NTHREADS, smem_bytes>>>(
        h0, W1, b1, W2, b2, anchors,
        out_h, out_align, out_div, out_ten, B);
}